// round 6
// baseline (speedup 1.0000x reference)
#include <cuda_runtime.h>
#include <math.h>

// ---------------- problem dims ----------------
#define TT        8192
#define INDIM     109
#define HDIM      1024
#define GDIM      4096           // 4*HDIM
#define NBLK      128            // LSTM blocks: 128 * 8 elems = 1024
#define EPB       8              // h-elements per block

// ---------------- device scratch ----------------
__device__ float g_xp[TT * GDIM];                 // 128 MB input projections
__device__ float g_h0[TT * HDIM];                 // 32 MB layer-0 h history
__device__ float g_h1[TT * HDIM];                 // 32 MB layer-1 h history
// combined publish line per block: word0 = seq, words 4..7 = h0..h3,
// words 8..11 = h4..h7 (64B per block, double-buffered by step parity)
__device__ __align__(64) unsigned g_pub[2][NBLK][16];

// ---------------- small helpers ----------------
__device__ __forceinline__ unsigned long long fma2(unsigned long long a,
                                                   unsigned long long b,
                                                   unsigned long long c) {
    unsigned long long d;
    asm("fma.rn.f32x2 %0, %1, %2, %3;" : "=l"(d) : "l"(a), "l"(b), "l"(c));
    return d;
}
__device__ __forceinline__ float2 unpack2(unsigned long long v) {
    float2 f;
    asm("mov.b64 {%0,%1}, %2;" : "=f"(f.x), "=f"(f.y) : "l"(v));
    return f;
}
__device__ __forceinline__ float fast_sigmoid(float x) {
    float e = __expf(-x);
    return __fdividef(1.f, 1.f + e);
}
__device__ __forceinline__ float fast_tanh(float x) {
    float e = __expf(-2.f * x);
    return fmaf(2.f, __fdividef(1.f, 1.f + e), -1.f);
}

__global__ void reset_state_kernel() {
    // 1024 threads, zero all pub lines (seq=0, h=0)
    unsigned* p = (unsigned*)g_pub;   // 2*128*16 = 4096 words
    int i = threadIdx.x;
#pragma unroll
    for (int q = 0; q < 4; q++) p[i * 4 + q] = 0u;
}

// ---------------- xp0: [T,109] @ [4096,109]^T + bias ----------------
__global__ __launch_bounds__(256) void gemm_xproj_small(
    const float* __restrict__ A,      // [T][109]
    const float* __restrict__ B,      // [4096][109]
    const float* __restrict__ bias1,
    const float* __restrict__ bias2)
{
    __shared__ float sA[64][113];
    __shared__ float sB[32][113];
    int t0 = blockIdx.x * 64;
    int r0 = blockIdx.y * 32;
    int tid = threadIdx.x;
    int tx = tid & 15;
    int ty = tid >> 4;

    for (int idx = tid; idx < 64 * INDIM; idx += 256) {
        int row = idx / INDIM, k = idx - row * INDIM;
        sA[row][k] = A[(size_t)(t0 + row) * INDIM + k];
    }
    for (int idx = tid; idx < 32 * INDIM; idx += 256) {
        int row = idx / INDIM, k = idx - row * INDIM;
        sB[row][k] = B[(size_t)(r0 + row) * INDIM + k];
    }
    __syncthreads();

    float acc[4][2];
#pragma unroll
    for (int i = 0; i < 4; i++)
#pragma unroll
        for (int j = 0; j < 2; j++) acc[i][j] = 0.f;

    for (int k = 0; k < INDIM; k++) {
        float a[4], b[2];
#pragma unroll
        for (int i = 0; i < 4; i++) a[i] = sA[ty * 4 + i][k];
#pragma unroll
        for (int j = 0; j < 2; j++) b[j] = sB[tx * 2 + j][k];
#pragma unroll
        for (int i = 0; i < 4; i++)
#pragma unroll
            for (int j = 0; j < 2; j++) acc[i][j] = fmaf(a[i], b[j], acc[i][j]);
    }

#pragma unroll
    for (int j = 0; j < 2; j++) {
        int r = r0 + tx * 2 + j;
        float bs = __ldg(&bias1[r]) + __ldg(&bias2[r]);
#pragma unroll
        for (int i = 0; i < 4; i++) {
            int t = t0 + ty * 4 + i;
            g_xp[(size_t)t * GDIM + r] = acc[i][j] + bs;
        }
    }
}

// ---------------- xp1: [T,1024] @ [4096,1024]^T + bias ----------------
__global__ __launch_bounds__(256) void gemm_xproj_big(
    const float* __restrict__ B,      // [4096][1024] = W_ih1
    const float* __restrict__ bias1,
    const float* __restrict__ bias2)
{
    __shared__ float sA[16][132];
    __shared__ float sB[16][132];
    const float* A = g_h0;            // [T][1024]
    int t0 = blockIdx.x * 128;
    int r0 = blockIdx.y * 128;
    int tid = threadIdx.x;
    int tx = tid & 15;
    int ty = tid >> 4;
    int loadrow = tid & 127;
    int loadq   = tid >> 7;

    float acc[8][8];
#pragma unroll
    for (int i = 0; i < 8; i++)
#pragma unroll
        for (int j = 0; j < 8; j++) acc[i][j] = 0.f;

    for (int kc = 0; kc < HDIM; kc += 16) {
        __syncthreads();
#pragma unroll
        for (int f = 0; f < 2; f++) {
            int kq = loadq * 2 + f;
            float4 v = __ldg((const float4*)(A + (size_t)(t0 + loadrow) * HDIM + kc) + kq);
            int kk = kq * 4;
            sA[kk + 0][loadrow] = v.x; sA[kk + 1][loadrow] = v.y;
            sA[kk + 2][loadrow] = v.z; sA[kk + 3][loadrow] = v.w;
            float4 w = __ldg((const float4*)(B + (size_t)(r0 + loadrow) * HDIM + kc) + kq);
            sB[kk + 0][loadrow] = w.x; sB[kk + 1][loadrow] = w.y;
            sB[kk + 2][loadrow] = w.z; sB[kk + 3][loadrow] = w.w;
        }
        __syncthreads();
#pragma unroll
        for (int k = 0; k < 16; k++) {
            float4 a0 = *(const float4*)&sA[k][ty * 8];
            float4 a1 = *(const float4*)&sA[k][ty * 8 + 4];
            float4 b0 = *(const float4*)&sB[k][tx * 8];
            float4 b1 = *(const float4*)&sB[k][tx * 8 + 4];
            float a[8] = {a0.x, a0.y, a0.z, a0.w, a1.x, a1.y, a1.z, a1.w};
            float b[8] = {b0.x, b0.y, b0.z, b0.w, b1.x, b1.y, b1.z, b1.w};
#pragma unroll
            for (int i = 0; i < 8; i++)
#pragma unroll
                for (int j = 0; j < 8; j++) acc[i][j] = fmaf(a[i], b[j], acc[i][j]);
        }
    }

    float bs[8];
#pragma unroll
    for (int j = 0; j < 8; j++) {
        int r = r0 + tx * 8 + j;
        bs[j] = __ldg(&bias1[r]) + __ldg(&bias2[r]);
    }
#pragma unroll
    for (int i = 0; i < 8; i++) {
        int t = t0 + ty * 8 + i;
        float* crow = g_xp + (size_t)t * GDIM + r0 + tx * 8;
        float4 o0 = make_float4(acc[i][0] + bs[0], acc[i][1] + bs[1],
                                acc[i][2] + bs[2], acc[i][3] + bs[3]);
        float4 o1 = make_float4(acc[i][4] + bs[4], acc[i][5] + bs[5],
                                acc[i][6] + bs[6], acc[i][7] + bs[7]);
        *(float4*)crow = o0;
        *(float4*)(crow + 4) = o1;
    }
}

// ---------------- LSTM recurrence: persistent, pub-line synced -------------
// 128 blocks x 256 threads. Block b owns h elems [8b, 8b+8).
// Warp j owns all four gate rows of element e = 8b + j; lane 0 does gates.
// Publish: 64B line per block = [seq | h0..h7]; two relaxed v4 + release seq.
// Poll (warp 0 only): acquire seq + relaxed h every iteration -> on success
// h is already in registers (one L2 round trip total).
// History: SMEM ring, dumped to DRAM by warp 1 every 16 steps AFTER release
// -> release membar never drains a DRAM store.
__global__ __launch_bounds__(256, 1) void lstm_layer_kernel(
    const float* __restrict__ Whh,    // [4096][1024]
    int out_sel)                      // 0 -> g_h0, 1 -> g_h1
{
    __shared__ float4 sH4[256];                   // h_t staging (4KB)
    __shared__ __align__(16) float sPub[8];       // this block's new h
    __shared__ float sHist[2][16][8];             // history ring (1KB)

    float* hout = out_sel ? g_h1 : g_h0;
    int b   = blockIdx.x;
    int tid = threadIdx.x;
    int w   = tid >> 5;
    int l   = tid & 31;
    int e   = (b << 3) + w;

    // ---- load this warp's 4 gate rows into registers ----
    ulonglong2 Wreg[4][8];
#pragma unroll
    for (int g = 0; g < 4; g++) {
        const ulonglong2* rowp =
            (const ulonglong2*)(Whh + (size_t)((g << 10) + e) * HDIM);
#pragma unroll
        for (int k = 0; k < 8; k++) Wreg[g][k] = rowp[l + 32 * k];
    }
    float creg = 0.f;

    // h_0 = 0
    sH4[tid] = make_float4(0.f, 0.f, 0.f, 0.f);
    __syncthreads();

    // prefetch xp for t=0
    float x0 = 0.f, x1 = 0.f, x2 = 0.f, x3 = 0.f;
    if (l == 0) {
        const float* p = g_xp + e;
        x0 = __ldg(p);
        x1 = __ldg(p + 1024);
        x2 = __ldg(p + 2048);
        x3 = __ldg(p + 3072);
    }

    for (int t = 0; t < TT; t++) {
        // prefetch xp for NEXT step
        float nx0 = 0.f, nx1 = 0.f, nx2 = 0.f, nx3 = 0.f;
        if (l == 0 && t + 1 < TT) {
            const float* p = g_xp + (size_t)(t + 1) * GDIM + e;
            nx0 = __ldg(p);
            nx1 = __ldg(p + 1024);
            nx2 = __ldg(p + 2048);
            nx3 = __ldg(p + 3072);
        }

        // ---- acquire h_t (warp 0 polls seq AND carries h in same iteration)
        if (t) {
            if (w == 0) {
                const unsigned need = (unsigned)t;
                const unsigned* base = &g_pub[t & 1][0][0];
                const unsigned* p0 = base + (size_t)(l      ) * 16;
                const unsigned* p1 = base + (size_t)(l + 32 ) * 16;
                const unsigned* p2 = base + (size_t)(l + 64 ) * 16;
                const unsigned* p3 = base + (size_t)(l + 96 ) * 16;
                unsigned s0, s1, s2, s3;
                float4 a0, a1, a2, a3, c0, c1, c2, c3;
                bool ok;
                do {
#define POLL1(S,A,C,P) \
    asm volatile("ld.acquire.gpu.global.u32 %0, [%1];" \
                 : "=r"(S) : "l"(P) : "memory"); \
    asm volatile("ld.relaxed.gpu.global.v4.f32 {%0,%1,%2,%3}, [%4];" \
                 : "=f"(A.x), "=f"(A.y), "=f"(A.z), "=f"(A.w) \
                 : "l"(P + 4) : "memory"); \
    asm volatile("ld.relaxed.gpu.global.v4.f32 {%0,%1,%2,%3}, [%4];" \
                 : "=f"(C.x), "=f"(C.y), "=f"(C.z), "=f"(C.w) \
                 : "l"(P + 8) : "memory");
                    POLL1(s0, a0, c0, p0)
                    POLL1(s1, a1, c1, p1)
                    POLL1(s2, a2, c2, p2)
                    POLL1(s3, a3, c3, p3)
#undef POLL1
                    ok = (s0 >= need) && (s1 >= need) &&
                         (s2 >= need) && (s3 >= need);
                } while (!__all_sync(0xffffffffu, ok));
                sH4[2 * l            ] = a0;  sH4[2 * l        + 1] = c0;
                sH4[2 * (l + 32)     ] = a1;  sH4[2 * (l + 32) + 1] = c1;
                sH4[2 * (l + 64)     ] = a2;  sH4[2 * (l + 64) + 1] = c2;
                sH4[2 * (l + 96)     ] = a3;  sH4[2 * (l + 96) + 1] = c3;
            }
            __syncthreads();
        }

        // ---- matvec: 4 gate rows x 32 col-quads per thread, f32x2 FMA ----
        const ulonglong2* sH2 = (const ulonglong2*)sH4;
        unsigned long long acc[4][2];
#pragma unroll
        for (int g = 0; g < 4; g++) { acc[g][0] = 0ull; acc[g][1] = 0ull; }
#pragma unroll
        for (int k = 0; k < 8; k++) {
            ulonglong2 hv = sH2[32 * k + l];
#pragma unroll
            for (int g = 0; g < 4; g++) {
                acc[g][0] = fma2(Wreg[g][k].x, hv.x, acc[g][0]);
                acc[g][1] = fma2(Wreg[g][k].y, hv.y, acc[g][1]);
            }
        }
        float dot[4];
#pragma unroll
        for (int g = 0; g < 4; g++) {
            float2 lo = unpack2(acc[g][0]);
            float2 hi = unpack2(acc[g][1]);
            float s = (lo.x + lo.y) + (hi.x + hi.y);
#pragma unroll
            for (int off = 16; off; off >>= 1)
                s += __shfl_xor_sync(0xffffffffu, s, off);
            dot[g] = s;
        }

        // ---- gate math (lane 0) ----
        if (l == 0) {
            float gi = dot[0] + x0;
            float gf = dot[1] + x1;
            float gg = dot[2] + x2;
            float go = dot[3] + x3;
            float si = fast_sigmoid(gi);
            float sf = fast_sigmoid(gf);
            float so = fast_sigmoid(go);
            float tg = fast_tanh(gg);
            float c  = fmaf(sf, creg, si * tg);
            creg = c;
            float h  = so * fast_tanh(c);
            sPub[w] = h;                          // for publish
            sHist[(t >> 4) & 1][t & 15][w] = h;   // for batched history
        }
        __syncthreads();

        // ---- publish (tid 0): relaxed h, release seq — L2 only ----
        if (tid == 0) {
            float4 hlo = *(const float4*)&sPub[0];
            float4 hhi = *(const float4*)&sPub[4];
            unsigned* line = &g_pub[(t + 1) & 1][b][0];
            asm volatile("st.relaxed.gpu.global.v4.f32 [%0], {%1,%2,%3,%4};"
                         :: "l"(line + 4), "f"(hlo.x), "f"(hlo.y),
                            "f"(hlo.z), "f"(hlo.w) : "memory");
            asm volatile("st.relaxed.gpu.global.v4.f32 [%0], {%1,%2,%3,%4};"
                         :: "l"(line + 8), "f"(hhi.x), "f"(hhi.y),
                            "f"(hhi.z), "f"(hhi.w) : "memory");
            asm volatile("st.release.gpu.global.u32 [%0], %1;"
                         :: "l"(line), "r"((unsigned)(t + 1)) : "memory");
        }

        // ---- history dump (warp 1, off the critical path, AFTER release) ----
        if ((t & 15) == 15 && w == 1) {
            int i = l;                       // 0..31
            if (i < 32) {
                int s = i >> 1, half = i & 1;
                const float4 v = *(const float4*)&sHist[(t >> 4) & 1][s][half * 4];
                __stcg((float4*)&hout[(size_t)(t - 15 + s) * HDIM + (b << 3) + half * 4], v);
            }
        }

        x0 = nx0; x1 = nx1; x2 = nx2; x3 = nx3;
    }
}

// ---------------- FC + log_softmax ----------------
__global__ __launch_bounds__(128) void fc_logsoftmax_kernel(
    const float* __restrict__ fcw,    // [109][1024]
    const float* __restrict__ fcb,    // [109]
    float* __restrict__ out)          // [T][109]
{
    __shared__ float sH[8 * 1024];
    __shared__ float sL[8][112];
    __shared__ float sLse[8];
    int t0 = blockIdx.x * 8;
    int tid = threadIdx.x;

    const float4* hg = (const float4*)(g_h1 + (size_t)t0 * HDIM);
    float4* sH4 = (float4*)sH;
#pragma unroll
    for (int q = 0; q < 16; q++) sH4[tid + 128 * q] = __ldg(hg + tid + 128 * q);
    __syncthreads();

    if (tid < INDIM) {
        float acc[8];
#pragma unroll
        for (int i = 0; i < 8; i++) acc[i] = 0.f;
        const float4* w4 = (const float4*)(fcw + (size_t)tid * HDIM);
        for (int k4 = 0; k4 < 256; k4++) {
            float4 w = __ldg(w4 + k4);
#pragma unroll
            for (int tt = 0; tt < 8; tt++) {
                float4 hv = sH4[tt * 256 + k4];
                acc[tt] = fmaf(w.x, hv.x,
                          fmaf(w.y, hv.y,
                          fmaf(w.z, hv.z,
                          fmaf(w.w, hv.w, acc[tt]))));
            }
        }
        float bb = __ldg(&fcb[tid]);
#pragma unroll
        for (int tt = 0; tt < 8; tt++) sL[tt][tid] = acc[tt] + bb;
    }
    __syncthreads();

    if (tid < 8) {
        float m = -1e30f;
        for (int n = 0; n < INDIM; n++) m = fmaxf(m, sL[tid][n]);
        float s = 0.f;
        for (int n = 0; n < INDIM; n++) s += expf(sL[tid][n] - m);
        sLse[tid] = m + logf(s);
    }
    __syncthreads();

    for (int idx = tid; idx < 8 * INDIM; idx += 128) {
        int tt = idx / INDIM, n = idx - tt * INDIM;
        out[(size_t)(t0 + tt) * INDIM + n] = sL[tt][n] - sLse[tt];
    }
}

// ---------------- launcher ----------------
extern "C" void kernel_launch(void* const* d_in, const int* in_sizes, int n_in,
                              void* d_out, int out_size) {
    const float* input = (const float*)d_in[0];
    const float* W_ih0 = (const float*)d_in[1];
    const float* W_hh0 = (const float*)d_in[2];
    const float* b_ih0 = (const float*)d_in[3];
    const float* b_hh0 = (const float*)d_in[4];
    const float* W_ih1 = (const float*)d_in[5];
    const float* W_hh1 = (const float*)d_in[6];
    const float* b_ih1 = (const float*)d_in[7];
    const float* b_hh1 = (const float*)d_in[8];
    const float* fc_w  = (const float*)d_in[9];
    const float* fc_b  = (const float*)d_in[10];
    float* out = (float*)d_out;

    // xp0 = input @ W_ih0^T + b_ih0 + b_hh0
    gemm_xproj_small<<<dim3(TT / 64, GDIM / 32), 256>>>(input, W_ih0, b_ih0, b_hh0);

    // layer 0 recurrence -> g_h0
    reset_state_kernel<<<1, 1024>>>();
    lstm_layer_kernel<<<NBLK, 256>>>(W_hh0, 0);

    // xp1 = h0 @ W_ih1^T + b_ih1 + b_hh1
    gemm_xproj_big<<<dim3(TT / 128, GDIM / 128), 256>>>(W_ih1, b_ih1, b_hh1);

    // layer 1 recurrence -> g_h1
    reset_state_kernel<<<1, 1024>>>();
    lstm_layer_kernel<<<NBLK, 256>>>(W_hh1, 1);

    // logits + log_softmax
    fc_logsoftmax_kernel<<<TT / 8, 128>>>(fc_w, fc_b, out);
}

// round 8
// speedup vs baseline: 2.5894x; 2.5894x over previous
#include <cuda_runtime.h>
#include <math.h>

// ---------------- problem dims ----------------
#define TT        8192
#define INDIM     109
#define HDIM      1024
#define GDIM      4096           // 4*HDIM
#define NBLK      128            // LSTM blocks: 128 * 8 elems = 1024
#define EPB       8              // h-elements per block

// ---------------- device scratch ----------------
__device__ float g_xp[TT * GDIM];                 // 128 MB: xp0 projections
__device__ float g_h1[TT * HDIM];                 // 32 MB layer-1 h history
// publish buffers: [parity][0..1023]=h0, [1024..2047]=h1 (float4-aligned)
__device__ __align__(16) float g_pubH[2][2048];
__device__ __align__(16) unsigned g_flag[NBLK];   // packed u32 flags (4 lines)

// ---------------- small helpers ----------------
__device__ __forceinline__ unsigned long long fma2(unsigned long long a,
                                                   unsigned long long b,
                                                   unsigned long long c) {
    unsigned long long d;
    asm("fma.rn.f32x2 %0, %1, %2, %3;" : "=l"(d) : "l"(a), "l"(b), "l"(c));
    return d;
}
__device__ __forceinline__ float2 unpack2(unsigned long long v) {
    float2 f;
    asm("mov.b64 {%0,%1}, %2;" : "=f"(f.x), "=f"(f.y) : "l"(v));
    return f;
}
__device__ __forceinline__ float fast_sigmoid(float x) {
    float e = __expf(-x);
    return __fdividef(1.f, 1.f + e);
}
__device__ __forceinline__ float fast_tanh(float x) {
    float e = __expf(-2.f * x);
    return fmaf(2.f, __fdividef(1.f, 1.f + e), -1.f);
}
__device__ __forceinline__ float warp_red4(float s) {
#pragma unroll
    for (int off = 16; off; off >>= 1)
        s += __shfl_xor_sync(0xffffffffu, s, off);
    return s;
}

__global__ void reset_state_kernel() {
    int i = threadIdx.x;                  // 1024 threads
    float* p = &g_pubH[0][0];             // 4096 floats total
#pragma unroll
    for (int q = 0; q < 4; q++) p[i + 1024 * q] = 0.f;
    if (i < NBLK) g_flag[i] = 0u;
}

// ---------------- xp0: [T,109] @ [4096,109]^T + bias ----------------
__global__ __launch_bounds__(256) void gemm_xproj_small(
    const float* __restrict__ A,      // [T][109]
    const float* __restrict__ B,      // [4096][109]
    const float* __restrict__ bias1,
    const float* __restrict__ bias2)
{
    __shared__ float sA[64][113];
    __shared__ float sB[32][113];
    int t0 = blockIdx.x * 64;
    int r0 = blockIdx.y * 32;
    int tid = threadIdx.x;
    int tx = tid & 15;
    int ty = tid >> 4;

    for (int idx = tid; idx < 64 * INDIM; idx += 256) {
        int row = idx / INDIM, k = idx - row * INDIM;
        sA[row][k] = A[(size_t)(t0 + row) * INDIM + k];
    }
    for (int idx = tid; idx < 32 * INDIM; idx += 256) {
        int row = idx / INDIM, k = idx - row * INDIM;
        sB[row][k] = B[(size_t)(r0 + row) * INDIM + k];
    }
    __syncthreads();

    float acc[4][2];
#pragma unroll
    for (int i = 0; i < 4; i++)
#pragma unroll
        for (int j = 0; j < 2; j++) acc[i][j] = 0.f;

    for (int k = 0; k < INDIM; k++) {
        float a[4], b[2];
#pragma unroll
        for (int i = 0; i < 4; i++) a[i] = sA[ty * 4 + i][k];
#pragma unroll
        for (int j = 0; j < 2; j++) b[j] = sB[tx * 2 + j][k];
#pragma unroll
        for (int i = 0; i < 4; i++)
#pragma unroll
            for (int j = 0; j < 2; j++) acc[i][j] = fmaf(a[i], b[j], acc[i][j]);
    }

#pragma unroll
    for (int j = 0; j < 2; j++) {
        int r = r0 + tx * 2 + j;
        float bs = __ldg(&bias1[r]) + __ldg(&bias2[r]);
#pragma unroll
        for (int i = 0; i < 4; i++) {
            int t = t0 + ty * 4 + i;
            g_xp[(size_t)t * GDIM + r] = acc[i][j] + bs;
        }
    }
}

// ---------------- fused 2-layer LSTM recurrence ----------------
// 128 blocks x 256 threads. Block b owns h0 AND h1 elems [8b, 8b+8).
// Warp w owns element e = 8b+w of both layers.
// Pipeline: at step s compute h0_s (layer 0) and h1_{s-2} (layer 1).
//   pre-poll  : dot1 = W_ih1 @ h0_{s-2}  +  W_hh1 @ h1_{s-3}   (SMEM+RF,
//               operands staged at step s-1 -> overlaps sync wait)
//   poll      : R5 barrier — warp 0, one ld.acquire.v4 per lane, 4 lines
//   stage     : h0_{s-1}, h1_{s-2} -> SMEM (ldcg)
//   post-poll : dot0 = W_hh0(RF) @ h0_{s-1};  gates; publish; release.
// SMEM: sWih1 131072 | sWhh1 81920 | sH0 4096 | sH1 4096 | sPub 256
#define FUS_SMEM (131072 + 81920 + 4096 + 4096 + 256)

__global__ __launch_bounds__(256, 1) void lstm_fused_kernel(
    const float* __restrict__ Whh0,   // [4096][1024]
    const float* __restrict__ Wih1,   // [4096][1024]
    const float* __restrict__ Whh1,   // [4096][1024]
    const float* __restrict__ b_ih1,
    const float* __restrict__ b_hh1)
{
    extern __shared__ char smem[];
    float4* sWih1 = (float4*)(smem);                            // 32 rows x 256 f4
    float4* sWhh1 = (float4*)(smem + 131072);                   // 32 rows x 160 f4
    float4* sH0   = (float4*)(smem + 131072 + 81920);           // 256 f4
    float4* sH1   = (float4*)(smem + 131072 + 81920 + 4096);    // 256 f4
    float*  sPub  = (float*)(smem + 131072 + 81920 + 8192);     // [0..7]=h0,[8..15]=h1

    int b   = blockIdx.x;
    int tid = threadIdx.x;
    int w   = tid >> 5;
    int l   = tid & 31;
    int e   = (b << 3) + w;

    // ---- RF weights ----
    ulonglong2 W0[4][8];              // W_hh0, full rows
    ulonglong2 W1r[4][3];             // W_hh1, k=5..7 (cols 640..1023)
#pragma unroll
    for (int g = 0; g < 4; g++) {
        const ulonglong2* r0p =
            (const ulonglong2*)(Whh0 + (size_t)((g << 10) + e) * HDIM);
        const ulonglong2* r1p =
            (const ulonglong2*)(Whh1 + (size_t)((g << 10) + e) * HDIM);
#pragma unroll
        for (int k = 0; k < 8; k++) W0[g][k] = r0p[l + 32 * k];
#pragma unroll
        for (int k = 0; k < 3; k++) W1r[g][k] = r1p[l + 32 * (5 + k)];
    }

    // ---- SMEM weights (cooperative) ----
    for (int idx = tid; idx < 32 * 256; idx += 256) {
        int rl = idx >> 8, c4 = idx & 255;
        int g = rl >> 3, ww = rl & 7;
        sWih1[idx] = ((const float4*)(Wih1 +
            (size_t)((g << 10) + (b << 3) + ww) * HDIM))[c4];
    }
    for (int idx = tid; idx < 32 * 160; idx += 256) {
        int rl = idx / 160, c4 = idx - rl * 160;
        int g = rl >> 3, ww = rl & 7;
        sWhh1[idx] = ((const float4*)(Whh1 +
            (size_t)((g << 10) + (b << 3) + ww) * HDIM))[c4];
    }

    // layer-1 bias sums (lane 0)
    float bs1[4];
    if (l == 0) {
#pragma unroll
        for (int g = 0; g < 4; g++) {
            int r = (g << 10) + e;
            bs1[g] = __ldg(&b_ih1[r]) + __ldg(&b_hh1[r]);
        }
    }

    // init SMEM h buffers + pub staging to zero
    sH0[tid] = make_float4(0.f, 0.f, 0.f, 0.f);
    sH1[tid] = make_float4(0.f, 0.f, 0.f, 0.f);
    if (tid < 16) sPub[tid] = 0.f;
    float c0 = 0.f, c1 = 0.f;
    __syncthreads();

    const uint4* flags4 = (const uint4*)g_flag;

    // prefetch xp0 for s=0
    float x0 = 0.f, x1 = 0.f, x2 = 0.f, x3 = 0.f;
    if (l == 0) {
        const float* p = g_xp + e;
        x0 = __ldg(p);
        x1 = __ldg(p + 1024);
        x2 = __ldg(p + 2048);
        x3 = __ldg(p + 3072);
    }

    const ulonglong2* H0 = (const ulonglong2*)sH0;
    const ulonglong2* H1 = (const ulonglong2*)sH1;
    const ulonglong2* wi = (const ulonglong2*)sWih1;
    const ulonglong2* wh = (const ulonglong2*)sWhh1;

    for (int s = 0; s <= TT + 1; s++) {
        // ===== pre-poll: layer-1 matvecs on previously staged vectors =====
        unsigned long long a1[4][2];
#pragma unroll
        for (int g = 0; g < 4; g++) { a1[g][0] = 0ull; a1[g][1] = 0ull; }
#pragma unroll
        for (int k = 0; k < 8; k++) {                 // W_ih1 @ h0_{s-2}
            ulonglong2 hv = H0[32 * k + l];
#pragma unroll
            for (int g = 0; g < 4; g++) {
                ulonglong2 wv = wi[(size_t)((g << 3) + w) * 256 + 32 * k + l];
                a1[g][0] = fma2(wv.x, hv.x, a1[g][0]);
                a1[g][1] = fma2(wv.y, hv.y, a1[g][1]);
            }
        }
#pragma unroll
        for (int k = 0; k < 5; k++) {                 // W_hh1(smem) @ h1_{s-3}
            ulonglong2 hv = H1[32 * k + l];
#pragma unroll
            for (int g = 0; g < 4; g++) {
                ulonglong2 wv = wh[(size_t)((g << 3) + w) * 160 + 32 * k + l];
                a1[g][0] = fma2(wv.x, hv.x, a1[g][0]);
                a1[g][1] = fma2(wv.y, hv.y, a1[g][1]);
            }
        }
#pragma unroll
        for (int k = 0; k < 3; k++) {                 // W_hh1(RF) @ h1_{s-3}
            ulonglong2 hv = H1[32 * (5 + k) + l];
#pragma unroll
            for (int g = 0; g < 4; g++) {
                a1[g][0] = fma2(W1r[g][k].x, hv.x, a1[g][0]);
                a1[g][1] = fma2(W1r[g][k].y, hv.y, a1[g][1]);
            }
        }
        float dot1[4];
#pragma unroll
        for (int g = 0; g < 4; g++) {
            float2 lo = unpack2(a1[g][0]);
            float2 hi = unpack2(a1[g][1]);
            dot1[g] = warp_red4((lo.x + lo.y) + (hi.x + hi.y));
        }

        // prefetch xp0 for next step (consumed one step later)
        float nx0 = 0.f, nx1 = 0.f, nx2 = 0.f, nx3 = 0.f;
        if (l == 0 && s + 1 < TT) {
            const float* p = g_xp + (size_t)(s + 1) * GDIM + e;
            nx0 = __ldg(p);
            nx1 = __ldg(p + 1024);
            nx2 = __ldg(p + 2048);
            nx3 = __ldg(p + 3072);
        }

        // ===== poll (R5 barrier, byte-for-byte) =====
        if (s) {
            if (w == 0) {
                unsigned need = (unsigned)s;
                bool ok;
                do {
                    uint4 v;
                    asm volatile(
                        "ld.acquire.gpu.global.v4.u32 {%0,%1,%2,%3}, [%4];"
                        : "=r"(v.x), "=r"(v.y), "=r"(v.z), "=r"(v.w)
                        : "l"(flags4 + l) : "memory");
                    ok = v.x >= need && v.y >= need && v.z >= need && v.w >= need;
                } while (!__all_sync(0xffffffffu, ok));
            }
        }
        __syncthreads();

        // ===== stage h0_{s-1}, h1_{s-2} =====
        {
            const float4* pub4 = (const float4*)g_pubH[s & 1];
            sH0[tid] = __ldcg(pub4 + tid);
            sH1[tid] = __ldcg(pub4 + 256 + tid);
        }
        __syncthreads();

        // ===== post-poll: layer-0 RF matvec on h0_{s-1} =====
        unsigned long long a0[4][2];
#pragma unroll
        for (int g = 0; g < 4; g++) { a0[g][0] = 0ull; a0[g][1] = 0ull; }
#pragma unroll
        for (int k = 0; k < 8; k++) {
            ulonglong2 hv = H0[32 * k + l];
#pragma unroll
            for (int g = 0; g < 4; g++) {
                a0[g][0] = fma2(W0[g][k].x, hv.x, a0[g][0]);
                a0[g][1] = fma2(W0[g][k].y, hv.y, a0[g][1]);
            }
        }
        float dot0[4];
#pragma unroll
        for (int g = 0; g < 4; g++) {
            float2 lo = unpack2(a0[g][0]);
            float2 hi = unpack2(a0[g][1]);
            dot0[g] = warp_red4((lo.x + lo.y) + (hi.x + hi.y));
        }

        // ===== gates (lane 0) =====
        float h1n = 0.f;
        if (l == 0) {
            if (s < TT) {                         // layer 0: h0_s
                float gi = dot0[0] + x0;
                float gf = dot0[1] + x1;
                float gg = dot0[2] + x2;
                float go = dot0[3] + x3;
                float si = fast_sigmoid(gi);
                float sf = fast_sigmoid(gf);
                float so = fast_sigmoid(go);
                float tg = fast_tanh(gg);
                c0 = fmaf(sf, c0, si * tg);
                sPub[w] = so * fast_tanh(c0);
            }
            if (s >= 2) {                         // layer 1: h1_{s-2}
                float gi = dot1[0] + bs1[0];
                float gf = dot1[1] + bs1[1];
                float gg = dot1[2] + bs1[2];
                float go = dot1[3] + bs1[3];
                float si = fast_sigmoid(gi);
                float sf = fast_sigmoid(gf);
                float so = fast_sigmoid(go);
                float tg = fast_tanh(gg);
                c1 = fmaf(sf, c1, si * tg);
                h1n = so * fast_tanh(c1);
                sPub[8 + w] = h1n;
            }
        }
        __syncthreads();

        // ===== publish (tid 0 only -> release covers its own stores) =====
        if (tid == 0) {
            float4 p0 = *(const float4*)&sPub[0];
            float4 p1 = *(const float4*)&sPub[4];
            float4 q0 = *(const float4*)&sPub[8];
            float4 q1 = *(const float4*)&sPub[12];
            float4* dst = (float4*)g_pubH[(s + 1) & 1];
            __stcg(dst + 2 * b,           p0);
            __stcg(dst + 2 * b + 1,       p1);
            __stcg(dst + 256 + 2 * b,     q0);
            __stcg(dst + 256 + 2 * b + 1, q1);
            asm volatile("st.release.gpu.global.u32 [%0], %1;"
                         :: "l"(&g_flag[b]), "r"((unsigned)(s + 1)) : "memory");
        }

        // ===== h1 history (off the release path) =====
        if (l == 0 && s >= 2) {
            __stcg(&g_h1[(size_t)(s - 2) * HDIM + e], h1n);
        }

        x0 = nx0; x1 = nx1; x2 = nx2; x3 = nx3;
    }
}

// ---------------- FC + log_softmax ----------------
__global__ __launch_bounds__(128) void fc_logsoftmax_kernel(
    const float* __restrict__ fcw,    // [109][1024]
    const float* __restrict__ fcb,    // [109]
    float* __restrict__ out)          // [T][109]
{
    __shared__ float sH[8 * 1024];
    __shared__ float sL[8][112];
    __shared__ float sLse[8];
    int t0 = blockIdx.x * 8;
    int tid = threadIdx.x;

    const float4* hg = (const float4*)(g_h1 + (size_t)t0 * HDIM);
    float4* sH4 = (float4*)sH;
#pragma unroll
    for (int q = 0; q < 16; q++) sH4[tid + 128 * q] = __ldg(hg + tid + 128 * q);
    __syncthreads();

    if (tid < INDIM) {
        float acc[8];
#pragma unroll
        for (int i = 0; i < 8; i++) acc[i] = 0.f;
        const float4* w4 = (const float4*)(fcw + (size_t)tid * HDIM);
        for (int k4 = 0; k4 < 256; k4++) {
            float4 w = __ldg(w4 + k4);
#pragma unroll
            for (int tt = 0; tt < 8; tt++) {
                float4 hv = sH4[tt * 256 + k4];
                acc[tt] = fmaf(w.x, hv.x,
                          fmaf(w.y, hv.y,
                          fmaf(w.z, hv.z,
                          fmaf(w.w, hv.w, acc[tt]))));
            }
        }
        float bb = __ldg(&fcb[tid]);
#pragma unroll
        for (int tt = 0; tt < 8; tt++) sL[tt][tid] = acc[tt] + bb;
    }
    __syncthreads();

    if (tid < 8) {
        float m = -1e30f;
        for (int n = 0; n < INDIM; n++) m = fmaxf(m, sL[tid][n]);
        float s = 0.f;
        for (int n = 0; n < INDIM; n++) s += expf(sL[tid][n] - m);
        sLse[tid] = m + logf(s);
    }
    __syncthreads();

    for (int idx = tid; idx < 8 * INDIM; idx += 128) {
        int tt = idx / INDIM, n = idx - tt * INDIM;
        out[(size_t)(t0 + tt) * INDIM + n] = sL[tt][n] - sLse[tt];
    }
}

// ---------------- launcher ----------------
extern "C" void kernel_launch(void* const* d_in, const int* in_sizes, int n_in,
                              void* d_out, int out_size) {
    const float* input = (const float*)d_in[0];
    const float* W_ih0 = (const float*)d_in[1];
    const float* W_hh0 = (const float*)d_in[2];
    const float* b_ih0 = (const float*)d_in[3];
    const float* b_hh0 = (const float*)d_in[4];
    const float* W_ih1 = (const float*)d_in[5];
    const float* W_hh1 = (const float*)d_in[6];
    const float* b_ih1 = (const float*)d_in[7];
    const float* b_hh1 = (const float*)d_in[8];
    const float* fc_w  = (const float*)d_in[9];
    const float* fc_b  = (const float*)d_in[10];
    float* out = (float*)d_out;

    cudaFuncSetAttribute(lstm_fused_kernel,
                         cudaFuncAttributeMaxDynamicSharedMemorySize, FUS_SMEM);

    // xp0 = input @ W_ih0^T + b_ih0 + b_hh0
    gemm_xproj_small<<<dim3(TT / 64, GDIM / 32), 256>>>(input, W_ih0, b_ih0, b_hh0);

    // fused 2-layer recurrence -> g_h1
    reset_state_kernel<<<1, 1024>>>();
    lstm_fused_kernel<<<NBLK, 256, FUS_SMEM>>>(W_hh0, W_ih1, W_hh1, b_ih1, b_hh1);

    // logits + log_softmax
    fc_logsoftmax_kernel<<<TT / 8, 128>>>(fc_w, fc_b, out);
}

// round 10
// speedup vs baseline: 2.6499x; 1.0234x over previous
#include <cuda_runtime.h>
#include <math.h>

// ---------------- problem dims ----------------
#define TT        8192
#define INDIM     109
#define HDIM      1024
#define GDIM      4096           // 4*HDIM
#define NBLK      128            // LSTM blocks: 128 * 8 elems = 1024
#define EPB       8              // h-elements per block

// ---------------- device scratch ----------------
__device__ float g_xp[TT * GDIM];                 // 128 MB: xp0 projections
__device__ float g_h1[TT * HDIM];                 // 32 MB layer-1 h history
// publish buffers: [parity][0..1023]=h0, [1024..2047]=h1 (float4-aligned)
__device__ __align__(16) float g_pubH[2][2048];
__device__ __align__(16) unsigned g_flag[NBLK];   // packed u32 flags (4 lines)

// ---------------- small helpers ----------------
__device__ __forceinline__ unsigned long long fma2(unsigned long long a,
                                                   unsigned long long b,
                                                   unsigned long long c) {
    unsigned long long d;
    asm("fma.rn.f32x2 %0, %1, %2, %3;" : "=l"(d) : "l"(a), "l"(b), "l"(c));
    return d;
}
__device__ __forceinline__ float2 unpack2(unsigned long long v) {
    float2 f;
    asm("mov.b64 {%0,%1}, %2;" : "=f"(f.x), "=f"(f.y) : "l"(v));
    return f;
}
__device__ __forceinline__ float fast_sigmoid(float x) {
    float e = __expf(-x);
    return __fdividef(1.f, 1.f + e);
}
__device__ __forceinline__ float fast_tanh(float x) {
    float e = __expf(-2.f * x);
    return fmaf(2.f, __fdividef(1.f, 1.f + e), -1.f);
}
__device__ __forceinline__ float warp_red4(float s) {
#pragma unroll
    for (int off = 16; off; off >>= 1)
        s += __shfl_xor_sync(0xffffffffu, s, off);
    return s;
}

__global__ void reset_state_kernel() {
    int i = threadIdx.x;                  // 1024 threads
    float* p = &g_pubH[0][0];             // 4096 floats total
#pragma unroll
    for (int q = 0; q < 4; q++) p[i + 1024 * q] = 0.f;
    if (i < NBLK) g_flag[i] = 0u;
}

// ---------------- xp0: [T,109] @ [4096,109]^T + bias ----------------
__global__ __launch_bounds__(256) void gemm_xproj_small(
    const float* __restrict__ A,      // [T][109]
    const float* __restrict__ B,      // [4096][109]
    const float* __restrict__ bias1,
    const float* __restrict__ bias2)
{
    __shared__ float sA[64][113];
    __shared__ float sB[32][113];
    int t0 = blockIdx.x * 64;
    int r0 = blockIdx.y * 32;
    int tid = threadIdx.x;
    int tx = tid & 15;
    int ty = tid >> 4;

    for (int idx = tid; idx < 64 * INDIM; idx += 256) {
        int row = idx / INDIM, k = idx - row * INDIM;
        sA[row][k] = A[(size_t)(t0 + row) * INDIM + k];
    }
    for (int idx = tid; idx < 32 * INDIM; idx += 256) {
        int row = idx / INDIM, k = idx - row * INDIM;
        sB[row][k] = B[(size_t)(r0 + row) * INDIM + k];
    }
    __syncthreads();

    float acc[4][2];
#pragma unroll
    for (int i = 0; i < 4; i++)
#pragma unroll
        for (int j = 0; j < 2; j++) acc[i][j] = 0.f;

    for (int k = 0; k < INDIM; k++) {
        float a[4], b[2];
#pragma unroll
        for (int i = 0; i < 4; i++) a[i] = sA[ty * 4 + i][k];
#pragma unroll
        for (int j = 0; j < 2; j++) b[j] = sB[tx * 2 + j][k];
#pragma unroll
        for (int i = 0; i < 4; i++)
#pragma unroll
            for (int j = 0; j < 2; j++) acc[i][j] = fmaf(a[i], b[j], acc[i][j]);
    }

#pragma unroll
    for (int j = 0; j < 2; j++) {
        int r = r0 + tx * 2 + j;
        float bs = __ldg(&bias1[r]) + __ldg(&bias2[r]);
#pragma unroll
        for (int i = 0; i < 4; i++) {
            int t = t0 + ty * 4 + i;
            g_xp[(size_t)t * GDIM + r] = acc[i][j] + bs;
        }
    }
}

// ---------------- fused 2-layer LSTM recurrence (CORRECT pipeline) --------
// 128 blocks x 256 threads. Block b owns h0 AND h1 elems [8b, 8b+8).
// Warp w owns element e = 8b+w of both layers.
// Step s computes h0_s (layer 0) and h1_{s-2} (layer 1).
//   pre-poll  : a1 = W_ih1 @ h0_{s-2}        (input path, lag-tolerant,
//               operand staged at step s-1 -> overlaps sync wait)
//   poll      : R5 barrier — warp 0, one ld.acquire.v4 per lane, 4 lines
//   stage     : h0_{s-1}, h1_{s-3} -> SMEM (ldcg, parity s&1)
//   post-poll : a0 = W_hh0(RF) @ h0_{s-1};
//               a1 += W_hh1(SMEM+RF) @ h1_{s-3}    <-- recurrent term MUST be
//               post-poll (distance-1 dependence); single 8-chain reduce;
//               gates; publish; release.
// SMEM: sWih1 131072 | sWhh1 81920 | sH0 4096 | sH1 4096 | sPub 256
#define FUS_SMEM (131072 + 81920 + 4096 + 4096 + 256)

__global__ __launch_bounds__(256, 1) void lstm_fused_kernel(
    const float* __restrict__ Whh0,   // [4096][1024]
    const float* __restrict__ Wih1,   // [4096][1024]
    const float* __restrict__ Whh1,   // [4096][1024]
    const float* __restrict__ b_ih1,
    const float* __restrict__ b_hh1)
{
    extern __shared__ char smem[];
    float4* sWih1 = (float4*)(smem);                            // 32 rows x 256 f4
    float4* sWhh1 = (float4*)(smem + 131072);                   // 32 rows x 160 f4
    float4* sH0   = (float4*)(smem + 131072 + 81920);           // 256 f4
    float4* sH1   = (float4*)(smem + 131072 + 81920 + 4096);    // 256 f4
    float*  sPub  = (float*)(smem + 131072 + 81920 + 8192);     // [0..7]=h0,[8..15]=h1

    int b   = blockIdx.x;
    int tid = threadIdx.x;
    int w   = tid >> 5;
    int l   = tid & 31;
    int e   = (b << 3) + w;

    // ---- RF weights ----
    ulonglong2 W0[4][8];              // W_hh0, full rows
    ulonglong2 W1r[4][3];             // W_hh1, k=5..7 (cols 640..1023)
#pragma unroll
    for (int g = 0; g < 4; g++) {
        const ulonglong2* r0p =
            (const ulonglong2*)(Whh0 + (size_t)((g << 10) + e) * HDIM);
        const ulonglong2* r1p =
            (const ulonglong2*)(Whh1 + (size_t)((g << 10) + e) * HDIM);
#pragma unroll
        for (int k = 0; k < 8; k++) W0[g][k] = r0p[l + 32 * k];
#pragma unroll
        for (int k = 0; k < 3; k++) W1r[g][k] = r1p[l + 32 * (5 + k)];
    }

    // ---- SMEM weights (cooperative) ----
    for (int idx = tid; idx < 32 * 256; idx += 256) {
        int rl = idx >> 8, c4 = idx & 255;
        int g = rl >> 3, ww = rl & 7;
        sWih1[idx] = ((const float4*)(Wih1 +
            (size_t)((g << 10) + (b << 3) + ww) * HDIM))[c4];
    }
    for (int idx = tid; idx < 32 * 160; idx += 256) {
        int rl = idx / 160, c4 = idx - rl * 160;
        int g = rl >> 3, ww = rl & 7;
        sWhh1[idx] = ((const float4*)(Whh1 +
            (size_t)((g << 10) + (b << 3) + ww) * HDIM))[c4];
    }

    // layer-1 bias sums (lane 0)
    float bs1[4];
    if (l == 0) {
#pragma unroll
        for (int g = 0; g < 4; g++) {
            int r = (g << 10) + e;
            bs1[g] = __ldg(&b_ih1[r]) + __ldg(&b_hh1[r]);
        }
    }

    // init SMEM h buffers + pub staging to zero
    sH0[tid] = make_float4(0.f, 0.f, 0.f, 0.f);
    sH1[tid] = make_float4(0.f, 0.f, 0.f, 0.f);
    if (tid < 16) sPub[tid] = 0.f;
    float c0 = 0.f, c1 = 0.f;
    __syncthreads();

    const uint4* flags4 = (const uint4*)g_flag;

    // prefetch xp0 for s=0
    float x0 = 0.f, x1 = 0.f, x2 = 0.f, x3 = 0.f;
    if (l == 0) {
        const float* p = g_xp + e;
        x0 = __ldg(p);
        x1 = __ldg(p + 1024);
        x2 = __ldg(p + 2048);
        x3 = __ldg(p + 3072);
    }

    const ulonglong2* H0 = (const ulonglong2*)sH0;
    const ulonglong2* H1 = (const ulonglong2*)sH1;
    const ulonglong2* wi = (const ulonglong2*)sWih1;
    const ulonglong2* wh = (const ulonglong2*)sWhh1;

    for (int s = 0; s <= TT + 1; s++) {
        // ===== pre-poll: W_ih1 @ h0_{s-2} (staged at step s-1) =====
        unsigned long long a1[4][2];
#pragma unroll
        for (int g = 0; g < 4; g++) { a1[g][0] = 0ull; a1[g][1] = 0ull; }
#pragma unroll
        for (int k = 0; k < 8; k++) {
            ulonglong2 hv = H0[32 * k + l];
#pragma unroll
            for (int g = 0; g < 4; g++) {
                ulonglong2 wv = wi[(size_t)((g << 3) + w) * 256 + 32 * k + l];
                a1[g][0] = fma2(wv.x, hv.x, a1[g][0]);
                a1[g][1] = fma2(wv.y, hv.y, a1[g][1]);
            }
        }

        // prefetch xp0 for next step (consumed one step later)
        float nx0 = 0.f, nx1 = 0.f, nx2 = 0.f, nx3 = 0.f;
        if (l == 0 && s + 1 < TT) {
            const float* p = g_xp + (size_t)(s + 1) * GDIM + e;
            nx0 = __ldg(p);
            nx1 = __ldg(p + 1024);
            nx2 = __ldg(p + 2048);
            nx3 = __ldg(p + 3072);
        }

        // ===== poll (R5 barrier, byte-for-byte) =====
        if (s) {
            if (w == 0) {
                unsigned need = (unsigned)s;
                bool ok;
                do {
                    uint4 v;
                    asm volatile(
                        "ld.acquire.gpu.global.v4.u32 {%0,%1,%2,%3}, [%4];"
                        : "=r"(v.x), "=r"(v.y), "=r"(v.z), "=r"(v.w)
                        : "l"(flags4 + l) : "memory");
                    ok = v.x >= need && v.y >= need && v.z >= need && v.w >= need;
                } while (!__all_sync(0xffffffffu, ok));
            }
        }
        __syncthreads();   // also separates pre-poll reads of sH0 from restage

        // ===== stage h0_{s-1}, h1_{s-3} =====
        {
            const float4* pub4 = (const float4*)g_pubH[s & 1];
            sH0[tid] = __ldcg(pub4 + tid);
            sH1[tid] = __ldcg(pub4 + 256 + tid);
        }
        __syncthreads();

        // ===== post-poll: W_hh0 @ h0_{s-1}  and  a1 += W_hh1 @ h1_{s-3} =====
        unsigned long long a0[4][2];
#pragma unroll
        for (int g = 0; g < 4; g++) { a0[g][0] = 0ull; a0[g][1] = 0ull; }
#pragma unroll
        for (int k = 0; k < 8; k++) {
            ulonglong2 h0v = H0[32 * k + l];
            ulonglong2 h1v = H1[32 * k + l];
#pragma unroll
            for (int g = 0; g < 4; g++) {
                a0[g][0] = fma2(W0[g][k].x, h0v.x, a0[g][0]);
                a0[g][1] = fma2(W0[g][k].y, h0v.y, a0[g][1]);
                ulonglong2 wv1 = (k < 5)
                    ? wh[(size_t)((g << 3) + w) * 160 + 32 * k + l]
                    : W1r[g][k - 5];
                a1[g][0] = fma2(wv1.x, h1v.x, a1[g][0]);
                a1[g][1] = fma2(wv1.y, h1v.y, a1[g][1]);
            }
        }

        // single 8-chain reduce (dot0 for layer 0, dot1 for layer 1)
        float dot0[4], dot1[4];
#pragma unroll
        for (int g = 0; g < 4; g++) {
            float2 lo0 = unpack2(a0[g][0]);
            float2 hi0 = unpack2(a0[g][1]);
            dot0[g] = warp_red4((lo0.x + lo0.y) + (hi0.x + hi0.y));
            float2 lo1 = unpack2(a1[g][0]);
            float2 hi1 = unpack2(a1[g][1]);
            dot1[g] = warp_red4((lo1.x + lo1.y) + (hi1.x + hi1.y));
        }

        // ===== gates (lane 0) =====
        float h1n = 0.f;
        if (l == 0) {
            if (s < TT) {                         // layer 0: h0_s
                float gi = dot0[0] + x0;
                float gf = dot0[1] + x1;
                float gg = dot0[2] + x2;
                float go = dot0[3] + x3;
                float si = fast_sigmoid(gi);
                float sf = fast_sigmoid(gf);
                float so = fast_sigmoid(go);
                float tg = fast_tanh(gg);
                c0 = fmaf(sf, c0, si * tg);
                sPub[w] = so * fast_tanh(c0);
            }
            if (s >= 2) {                         // layer 1: h1_{s-2}
                float gi = dot1[0] + bs1[0];
                float gf = dot1[1] + bs1[1];
                float gg = dot1[2] + bs1[2];
                float go = dot1[3] + bs1[3];
                float si = fast_sigmoid(gi);
                float sf = fast_sigmoid(gf);
                float so = fast_sigmoid(go);
                float tg = fast_tanh(gg);
                c1 = fmaf(sf, c1, si * tg);
                h1n = so * fast_tanh(c1);
                sPub[8 + w] = h1n;
            }
        }
        __syncthreads();

        // ===== publish (tid 0 only -> release covers its own stores) =====
        if (tid == 0) {
            float4 p0 = *(const float4*)&sPub[0];
            float4 p1 = *(const float4*)&sPub[4];
            float4 q0 = *(const float4*)&sPub[8];
            float4 q1 = *(const float4*)&sPub[12];
            float4* dst = (float4*)g_pubH[(s + 1) & 1];
            __stcg(dst + 2 * b,           p0);
            __stcg(dst + 2 * b + 1,       p1);
            __stcg(dst + 256 + 2 * b,     q0);
            __stcg(dst + 256 + 2 * b + 1, q1);
            asm volatile("st.release.gpu.global.u32 [%0], %1;"
                         :: "l"(&g_flag[b]), "r"((unsigned)(s + 1)) : "memory");
        }

        // ===== h1 history (off the release path) =====
        if (l == 0 && s >= 2) {
            __stcg(&g_h1[(size_t)(s - 2) * HDIM + e], h1n);
        }

        x0 = nx0; x1 = nx1; x2 = nx2; x3 = nx3;
    }
}

// ---------------- FC + log_softmax ----------------
__global__ __launch_bounds__(128) void fc_logsoftmax_kernel(
    const float* __restrict__ fcw,    // [109][1024]
    const float* __restrict__ fcb,    // [109]
    float* __restrict__ out)          // [T][109]
{
    __shared__ float sH[8 * 1024];
    __shared__ float sL[8][112];
    __shared__ float sLse[8];
    int t0 = blockIdx.x * 8;
    int tid = threadIdx.x;

    const float4* hg = (const float4*)(g_h1 + (size_t)t0 * HDIM);
    float4* sH4 = (float4*)sH;
#pragma unroll
    for (int q = 0; q < 16; q++) sH4[tid + 128 * q] = __ldg(hg + tid + 128 * q);
    __syncthreads();

    if (tid < INDIM) {
        float acc[8];
#pragma unroll
        for (int i = 0; i < 8; i++) acc[i] = 0.f;
        const float4* w4 = (const float4*)(fcw + (size_t)tid * HDIM);
        for (int k4 = 0; k4 < 256; k4++) {
            float4 w = __ldg(w4 + k4);
#pragma unroll
            for (int tt = 0; tt < 8; tt++) {
                float4 hv = sH4[tt * 256 + k4];
                acc[tt] = fmaf(w.x, hv.x,
                          fmaf(w.y, hv.y,
                          fmaf(w.z, hv.z,
                          fmaf(w.w, hv.w, acc[tt]))));
            }
        }
        float bb = __ldg(&fcb[tid]);
#pragma unroll
        for (int tt = 0; tt < 8; tt++) sL[tt][tid] = acc[tt] + bb;
    }
    __syncthreads();

    if (tid < 8) {
        float m = -1e30f;
        for (int n = 0; n < INDIM; n++) m = fmaxf(m, sL[tid][n]);
        float s = 0.f;
        for (int n = 0; n < INDIM; n++) s += expf(sL[tid][n] - m);
        sLse[tid] = m + logf(s);
    }
    __syncthreads();

    for (int idx = tid; idx < 8 * INDIM; idx += 128) {
        int tt = idx / INDIM, n = idx - tt * INDIM;
        out[(size_t)(t0 + tt) * INDIM + n] = sL[tt][n] - sLse[tt];
    }
}

// ---------------- launcher ----------------
extern "C" void kernel_launch(void* const* d_in, const int* in_sizes, int n_in,
                              void* d_out, int out_size) {
    const float* input = (const float*)d_in[0];
    const float* W_ih0 = (const float*)d_in[1];
    const float* W_hh0 = (const float*)d_in[2];
    const float* b_ih0 = (const float*)d_in[3];
    const float* b_hh0 = (const float*)d_in[4];
    const float* W_ih1 = (const float*)d_in[5];
    const float* W_hh1 = (const float*)d_in[6];
    const float* b_ih1 = (const float*)d_in[7];
    const float* b_hh1 = (const float*)d_in[8];
    const float* fc_w  = (const float*)d_in[9];
    const float* fc_b  = (const float*)d_in[10];
    float* out = (float*)d_out;

    cudaFuncSetAttribute(lstm_fused_kernel,
                         cudaFuncAttributeMaxDynamicSharedMemorySize, FUS_SMEM);

    // xp0 = input @ W_ih0^T + b_ih0 + b_hh0
    gemm_xproj_small<<<dim3(TT / 64, GDIM / 32), 256>>>(input, W_ih0, b_ih0, b_hh0);

    // fused 2-layer recurrence -> g_h1
    reset_state_kernel<<<1, 1024>>>();
    lstm_fused_kernel<<<NBLK, 256, FUS_SMEM>>>(W_hh0, W_ih1, W_hh1, b_ih1, b_hh1);

    // logits + log_softmax
    fc_logsoftmax_kernel<<<TT / 8, 128>>>(fc_w, fc_b, out);
}